// round 13
// baseline (speedup 1.0000x reference)
#include <cuda_runtime.h>
#include <cuda_fp16.h>
#include <cstdint>
#include <math.h>

#define NN 50000
#define EE 500000
#define ETOT (EE + NN)
#define CC 256
#define DD 128
#define NB_SCAN 49   // ceil(50000/1024)

// ---------------- scratch (static __device__, no allocation) ----------------
__device__ __half g_xf16[(size_t)NN * DD];   // x in fp16 (layer-1 gather source)
__device__ __half g_agg[(size_t)NN * CC];    // aggregated features (both layers)
__device__ __half g_af16[(size_t)NN * CC];   // x1 (layer-2 gather source)
__device__ __half g_w1f16[256 * 128];
__device__ __half g_w2f16[256 * 256];
__device__ float g_w1s[128], g_w1d[128];     // W1^T a1s / a1d
__device__ float g_w2s[256], g_w2d[256];     // W2^T a2s / a2d
__device__ float g_esrc[NN];
__device__ float g_edst[NN];
__device__ int   g_deg[NN];
__device__ int   g_rowptr[NN + 1];
__device__ int   g_cursor[NN];
__device__ int   g_col[ETOT];
__device__ int   g_bsum[NB_SCAN];

// ---------------- helpers ----------------
__device__ __forceinline__ uint32_t smem_u32(const void* p) {
    uint32_t a;
    asm("{ .reg .u64 t; cvta.to.shared.u64 t, %1; cvt.u32.u64 %0, t; }"
        : "=r"(a) : "l"(p));
    return a;
}

#define LDSM4(R, addr) \
    asm volatile("ldmatrix.sync.aligned.m8n8.x4.shared.b16 {%0,%1,%2,%3}, [%4];" \
                 : "=r"((R)[0]), "=r"((R)[1]), "=r"((R)[2]), "=r"((R)[3]) \
                 : "r"(addr))

#define MMA_FP16(d, a, b0, b1) \
    asm volatile("mma.sync.aligned.m16n8k16.row.col.f32.f16.f16.f32 " \
                 "{%0,%1,%2,%3},{%4,%5,%6,%7},{%8,%9},{%0,%1,%2,%3};" \
                 : "+f"((d)[0]), "+f"((d)[1]), "+f"((d)[2]), "+f"((d)[3]) \
                 : "r"((a)[0]), "r"((a)[1]), "r"((a)[2]), "r"((a)[3]), \
                   "r"(b0), "r"(b1))

#define CP16(smem_addr, gptr) \
    asm volatile("cp.async.cg.shared.global [%0], [%1], 16;" \
                 :: "r"(smem_addr), "l"(gptr))
#define CP_COMMIT() asm volatile("cp.async.commit_group;" ::: "memory")
#define CP_WAIT0()  asm volatile("cp.async.wait_group 0;" ::: "memory")

// ---------------- tiny: w-vectors (W^T @ a) ----------------
__global__ void wvec_kernel(const float* __restrict__ W1,
                            const float* __restrict__ a1s,
                            const float* __restrict__ a1d,
                            const float* __restrict__ W2,
                            const float* __restrict__ a2s,
                            const float* __restrict__ a2d) {
    int c = threadIdx.x;   // 256 threads
    if (c < 128) {
        float s = 0.f, d = 0.f;
        for (int h = 0; h < 256; h++) {
            float w = W1[h * 128 + c];
            s += w * a1s[h];
            d += w * a1d[h];
        }
        g_w1s[c] = s;
        g_w1d[c] = d;
    }
    {
        float s = 0.f, d = 0.f;
        for (int h = 0; h < 256; h++) {
            float w = W2[h * 256 + c];
            s += w * a2s[h];
            d += w * a2d[h];
        }
        g_w2s[c] = s;
        g_w2d[c] = d;
    }
}

// ---------------- prep: fp16 conversions ----------------
__global__ void prep_kernel(const float* __restrict__ x,
                            const float* __restrict__ W1,
                            const float* __restrict__ W2) {
    int i = blockIdx.x * blockDim.x + threadIdx.x;
    if (i < NN * DD)    g_xf16[i]  = __float2half(x[i]);
    if (i < 256 * 128)  g_w1f16[i] = __float2half(W1[i]);
    if (i < 256 * 256)  g_w2f16[i] = __float2half(W2[i]);
}

// ---------------- layer-1 e dots: GEMV x · w1s/w1d, warp per node ----------------
__global__ void gemv_kernel(const float* __restrict__ x) {
    int w = (blockIdx.x * blockDim.x + threadIdx.x) >> 5;
    if (w >= NN) return;
    int lane = threadIdx.x & 31;
    float4 v = *(const float4*)&x[(size_t)w * DD + lane * 4];
    float4 s = *(const float4*)&g_w1s[lane * 4];
    float4 d = *(const float4*)&g_w1d[lane * 4];
    float es = v.x * s.x + v.y * s.y + v.z * s.z + v.w * s.w;
    float ed = v.x * d.x + v.y * d.y + v.z * d.z + v.w * d.w;
    #pragma unroll
    for (int o = 16; o; o >>= 1) {
        es += __shfl_xor_sync(0xFFFFFFFFu, es, o);
        ed += __shfl_xor_sync(0xFFFFFFFFu, ed, o);
    }
    if (lane == 0) { g_esrc[w] = es; g_edst[w] = ed; }
}

// ---------------- CSR build ----------------
__global__ void zero_deg_kernel() {
    int i = blockIdx.x * blockDim.x + threadIdx.x;
    if (i < NN) g_deg[i] = 0;
}

__global__ void count_deg_kernel(const int* __restrict__ ei) {
    int i = blockIdx.x * blockDim.x + threadIdx.x;
    if (i >= ETOT) return;
    int d = (i < EE) ? ei[EE + i] : (i - EE);
    atomicAdd(&g_deg[d], 1);
}

__global__ void scan1_kernel() {
    __shared__ int sh[1024];
    int t = threadIdx.x;
    int i = blockIdx.x * 1024 + t;
    int v = (i < NN) ? g_deg[i] : 0;
    sh[t] = v;
    __syncthreads();
    #pragma unroll
    for (int off = 1; off < 1024; off <<= 1) {
        int x = (t >= off) ? sh[t - off] : 0;
        __syncthreads();
        sh[t] += x;
        __syncthreads();
    }
    if (i < NN) g_rowptr[i + 1] = sh[t];
    if (t == 1023) g_bsum[blockIdx.x] = sh[1023];
}

__global__ void scan2_kernel() {
    __shared__ int sh[64];
    int t = threadIdx.x;
    int v = (t < NB_SCAN) ? g_bsum[t] : 0;
    sh[t] = v;
    __syncthreads();
    #pragma unroll
    for (int o = 1; o < 64; o <<= 1) {
        int x = (t >= o) ? sh[t - o] : 0;
        __syncthreads();
        sh[t] += x;
        __syncthreads();
    }
    if (t < NB_SCAN) g_bsum[t] = sh[t] - v;   // exclusive
}

__global__ void scan3_kernel() {
    int t = threadIdx.x;
    int i = blockIdx.x * 1024 + t;
    if (i < NN) {
        int r = g_rowptr[i + 1] + g_bsum[blockIdx.x];
        g_rowptr[i + 1] = r;
        if (i + 1 < NN) g_cursor[i + 1] = r;
        if (i == 0) { g_rowptr[0] = 0; g_cursor[0] = 0; }
    }
}

__global__ void fill_kernel(const int* __restrict__ ei) {
    int i = blockIdx.x * blockDim.x + threadIdx.x;
    if (i >= ETOT) return;
    int s, d;
    if (i < EE) { s = ei[i]; d = ei[EE + i]; }
    else        { s = i - EE; d = s; }
    int pos = atomicAdd(&g_cursor[d], 1);
    g_col[pos] = s;
}

// ---------------- softmax + aggregate (input space): 2 warps/node, 2-edge unroll ----
// LAYER 1: gather x (128 ch), write agg (128 ch). LAYER 2: gather x1 (256 ch).
template <int LAYER>
__global__ void aggregate_kernel() {
    constexpr int CH = (LAYER == 1) ? DD : CC;
    constexpr int CPL = CH / 64;   // channels per lane: 2 or 4
    const __half* __restrict__ SRC = (LAYER == 1) ? g_xf16 : g_af16;

    int gw = (blockIdx.x * blockDim.x + threadIdx.x) >> 5;
    int w = gw >> 1;
    int hf = gw & 1;
    if (w >= NN) return;
    int lane = threadIdx.x & 31;
    int c0 = hf * (CH / 2) + lane * CPL;

    float edst = g_edst[w];
    int beg = g_rowptr[w];
    int end = g_rowptr[w + 1];

    float sum = 0.f;
    float a0 = 0.f, a1 = 0.f, a2 = 0.f, a3 = 0.f;

    int j = beg;
    for (; j + 1 < end; j += 2) {
        int s0 = g_col[j];
        int s1 = g_col[j + 1];
        float e0 = g_esrc[s0];
        float e1 = g_esrc[s1];
        uint2 u0, u1;
        if (CPL == 4) {
            u0 = *(const uint2*)&SRC[(size_t)s0 * CH + c0];
            u1 = *(const uint2*)&SRC[(size_t)s1 * CH + c0];
        } else {
            u0.x = *(const uint32_t*)&SRC[(size_t)s0 * CH + c0];
            u1.x = *(const uint32_t*)&SRC[(size_t)s1 * CH + c0];
        }

        float ea = e0 + edst;
        ea = ea > 0.f ? ea : 0.2f * ea;
        float p0 = __expf(ea);
        sum += p0;
        float2 f = __half22float2(*(__half2*)&u0.x);
        a0 += p0 * f.x; a1 += p0 * f.y;
        if (CPL == 4) {
            float2 g = __half22float2(*(__half2*)&u0.y);
            a2 += p0 * g.x; a3 += p0 * g.y;
        }

        float eb = e1 + edst;
        eb = eb > 0.f ? eb : 0.2f * eb;
        float p1 = __expf(eb);
        sum += p1;
        float2 f1 = __half22float2(*(__half2*)&u1.x);
        a0 += p1 * f1.x; a1 += p1 * f1.y;
        if (CPL == 4) {
            float2 g1 = __half22float2(*(__half2*)&u1.y);
            a2 += p1 * g1.x; a3 += p1 * g1.y;
        }
    }
    if (j < end) {
        int s0 = g_col[j];
        float e0 = g_esrc[s0];
        uint2 u0;
        if (CPL == 4) u0 = *(const uint2*)&SRC[(size_t)s0 * CH + c0];
        else          u0.x = *(const uint32_t*)&SRC[(size_t)s0 * CH + c0];
        float ea = e0 + edst;
        ea = ea > 0.f ? ea : 0.2f * ea;
        float p0 = __expf(ea);
        sum += p0;
        float2 f = __half22float2(*(__half2*)&u0.x);
        a0 += p0 * f.x; a1 += p0 * f.y;
        if (CPL == 4) {
            float2 g = __half22float2(*(__half2*)&u0.y);
            a2 += p0 * g.x; a3 += p0 * g.y;
        }
    }

    float inv = 1.f / (sum + 1e-16f);
    *(__half2*)&g_agg[(size_t)w * CH + c0] = __floats2half2_rn(a0 * inv, a1 * inv);
    if (CPL == 4)
        *(__half2*)&g_agg[(size_t)w * CH + c0 + 2] = __floats2half2_rn(a2 * inv, a3 * inv);
}

// ---------------- HMMA GEMM (fp16, 128x256 full-N): out = relu(agg@W^T + b) ----------
// LAYER 1 epilogue also writes x1 (fp16) and fused layer-2 e dots (w2s/w2d).
#define SST 40                       // smem row stride (fp16), conflict-free
#define ABYTES (128 * SST * 2)       // 10240
#define BBYTES (256 * SST * 2)       // 20480
#define STAGE_B (ABYTES + BBYTES)    // 30720
#define SM_TOTAL (2 * STAGE_B)       // 61440

template <int K, int LAYER>
__global__ __launch_bounds__(256) void mma_gemm_kernel(const float* __restrict__ bias,
                                                       float* __restrict__ out) {
    extern __shared__ __align__(16) char dsm[];
    __shared__ float sas[256], sad[256], sbb[256], sds[128], sdd[128];

    const __half* __restrict__ Af = g_agg;
    const __half* __restrict__ Wf = (LAYER == 1) ? g_w1f16 : g_w2f16;

    int tid = threadIdx.x;
    int wid = tid >> 5;
    int lane = tid & 31;
    int bm = blockIdx.x * 128;
    int wm = (wid & 1) * 64;
    int wn = (wid >> 1) * 64;

    uint32_t sbase = smem_u32(dsm);

    if (tid < 256) {
        sbb[tid] = bias[tid];
        if (LAYER == 1) {
            sas[tid] = g_w2s[tid];
            sad[tid] = g_w2d[tid];
        }
    }
    if (tid < 128) { sds[tid] = 0.f; sdd[tid] = 0.f; }

    float acc[4][8][4];
    #pragma unroll
    for (int a = 0; a < 4; a++)
        #pragma unroll
        for (int b = 0; b < 8; b++)
            #pragma unroll
            for (int c = 0; c < 4; c++) acc[a][b][c] = 0.f;

    const int nchunk = K >> 5;

    auto load_chunk = [&](int c, int st) {
        int k0 = c * 32;
        uint32_t sA = sbase + st * STAGE_B;
        uint32_t sB = sA + ABYTES;
        #pragma unroll
        for (int it = 0; it < 2; it++) {
            int idx = tid + it * 256;
            int r = idx >> 2;
            int q = (idx & 3) << 3;
            int row = bm + r;
            if (row > NN - 1) row = NN - 1;
            CP16(sA + (uint32_t)(r * SST + q) * 2, &Af[(size_t)row * K + k0 + q]);
        }
        #pragma unroll
        for (int it = 0; it < 4; it++) {
            int idx = tid + it * 256;
            int r = idx >> 2;
            int q = (idx & 3) << 3;
            CP16(sB + (uint32_t)(r * SST + q) * 2, &Wf[(size_t)r * K + k0 + q]);
        }
    };

    int a_row = wm + (lane & 15);
    int a_k8  = (lane >> 4) << 3;
    int b_row = wn + (lane & 7) + ((lane >> 4) << 3);
    int b_k8  = ((lane >> 3) & 1) << 3;

    load_chunk(0, 0);
    CP_COMMIT();

    for (int c = 0; c < nchunk; c++) {
        int st = c & 1;
        CP_WAIT0();
        __syncthreads();
        if (c + 1 < nchunk) {
            load_chunk(c + 1, (c + 1) & 1);
            CP_COMMIT();
        }

        uint32_t sA = sbase + st * STAGE_B;
        uint32_t sB = sA + ABYTES;

        #pragma unroll
        for (int ks = 0; ks < 2; ks++) {
            int kk = ks * 16;
            uint32_t aF[4][4];
            #pragma unroll
            for (int mt = 0; mt < 4; mt++) {
                uint32_t off = (uint32_t)(((a_row + mt * 16) * SST + kk + a_k8) * 2);
                LDSM4(aF[mt], sA + off);
            }
            uint32_t bF[4][4];
            #pragma unroll
            for (int bt = 0; bt < 4; bt++) {
                uint32_t off = (uint32_t)(((b_row + bt * 16) * SST + kk + b_k8) * 2);
                LDSM4(bF[bt], sB + off);
            }
            #pragma unroll
            for (int mt = 0; mt < 4; mt++) {
                #pragma unroll
                for (int nt = 0; nt < 8; nt++) {
                    int bt = nt >> 1;
                    int sbi = (nt & 1) * 2;
                    MMA_FP16(acc[mt][nt], aF[mt], bF[bt][sbi], bF[bt][sbi + 1]);
                }
            }
        }
        __syncthreads();
    }

    // ---- epilogue: bias + relu, write out (fp32); L1: x1 fp16 + fused e2 dots ----
    int gid = lane >> 2;
    int tig = lane & 3;
    const int OB = (LAYER == 1) ? 0 : 256;
    #pragma unroll
    for (int mt = 0; mt < 4; mt++) {
        float ds0 = 0.f, ds1 = 0.f, dd0 = 0.f, dd1 = 0.f;
        #pragma unroll
        for (int nt = 0; nt < 8; nt++) {
            int col = wn + nt * 8 + tig * 2;
            int row0 = bm + wm + mt * 16 + gid;
            int row1 = row0 + 8;
            float b0 = sbb[col], b1v = sbb[col + 1];
            float v0 = fmaxf(acc[mt][nt][0] + b0, 0.f);
            float v1 = fmaxf(acc[mt][nt][1] + b1v, 0.f);
            float v2 = fmaxf(acc[mt][nt][2] + b0, 0.f);
            float v3 = fmaxf(acc[mt][nt][3] + b1v, 0.f);
            if (row0 < NN) {
                *(float2*)&out[(size_t)row0 * 512 + OB + col] = make_float2(v0, v1);
                if (LAYER == 1)
                    *(__half2*)&g_af16[(size_t)row0 * CC + col] = __floats2half2_rn(v0, v1);
            }
            if (row1 < NN) {
                *(float2*)&out[(size_t)row1 * 512 + OB + col] = make_float2(v2, v3);
                if (LAYER == 1)
                    *(__half2*)&g_af16[(size_t)row1 * CC + col] = __floats2half2_rn(v2, v3);
            }
            if (LAYER == 1) {
                float as0 = sas[col], as1 = sas[col + 1];
                float ad0 = sad[col], ad1 = sad[col + 1];
                ds0 += v0 * as0 + v1 * as1;
                dd0 += v0 * ad0 + v1 * ad1;
                ds1 += v2 * as0 + v3 * as1;
                dd1 += v2 * ad0 + v3 * ad1;
            }
        }
        if (LAYER == 1) {
            #pragma unroll
            for (int o = 1; o <= 2; o <<= 1) {
                ds0 += __shfl_xor_sync(0xFFFFFFFFu, ds0, o);
                ds1 += __shfl_xor_sync(0xFFFFFFFFu, ds1, o);
                dd0 += __shfl_xor_sync(0xFFFFFFFFu, dd0, o);
                dd1 += __shfl_xor_sync(0xFFFFFFFFu, dd1, o);
            }
            if (tig == 0) {
                int lr = wm + mt * 16 + gid;
                atomicAdd(&sds[lr], ds0);
                atomicAdd(&sdd[lr], dd0);
                atomicAdd(&sds[lr + 8], ds1);
                atomicAdd(&sdd[lr + 8], dd1);
            }
        }
    }
    if (LAYER == 1) {
        __syncthreads();
        if (tid < 128) {
            int row = bm + tid;
            if (row < NN) {
                g_esrc[row] = sds[tid];
                g_edst[row] = sdd[tid];
            }
        }
    }
}

// ---------------- launch ----------------
extern "C" void kernel_launch(void* const* d_in, const int* in_sizes, int n_in,
                              void* d_out, int out_size) {
    const float* x    = (const float*)d_in[0];
    const int*   ei   = (const int*)d_in[1];
    const float* W1   = (const float*)d_in[2];
    const float* a1s  = (const float*)d_in[3];
    const float* a1d  = (const float*)d_in[4];
    const float* b1   = (const float*)d_in[5];
    const float* W2   = (const float*)d_in[6];
    const float* a2s  = (const float*)d_in[7];
    const float* a2d  = (const float*)d_in[8];
    const float* b2   = (const float*)d_in[9];
    float* out = (float*)d_out;

    static cudaStream_t strB = nullptr;
    static cudaEvent_t evFork = nullptr, evJoin = nullptr;
    if (!strB) {
        cudaStreamCreateWithFlags(&strB, cudaStreamNonBlocking);
        cudaEventCreateWithFlags(&evFork, cudaEventDisableTiming);
        cudaEventCreateWithFlags(&evJoin, cudaEventDisableTiming);
        cudaFuncSetAttribute(mma_gemm_kernel<128, 1>,
                             cudaFuncAttributeMaxDynamicSharedMemorySize, SM_TOTAL);
        cudaFuncSetAttribute(mma_gemm_kernel<256, 2>,
                             cudaFuncAttributeMaxDynamicSharedMemorySize, SM_TOTAL);
    }
    cudaStream_t s0 = (cudaStream_t)0;

    dim3 ggrid((NN + 127) / 128, 1);
    int agg_blocks = (NN * 2 + 7) / 8;    // 2 warps per node, 8 warps/block
    int gemv_blocks = (NN + 7) / 8;

    cudaEventRecord(evFork, s0);
    cudaStreamWaitEvent(strB, evFork, 0);

    wvec_kernel<<<1, 256, 0, s0>>>(W1, a1s, a1d, W2, a2s, a2d);             // 0
    prep_kernel<<<(NN * DD + 255) / 256, 256, 0, s0>>>(x, W1, W2);          // 1
    zero_deg_kernel<<<(NN + 255) / 256, 256, 0, strB>>>();                  // 2
    gemv_kernel<<<gemv_blocks, 256, 0, s0>>>(x);                            // 3 (ncu)
    count_deg_kernel<<<(ETOT + 255) / 256, 256, 0, strB>>>(ei);             // 4
    scan1_kernel<<<NB_SCAN, 1024, 0, strB>>>();                             // 5
    scan2_kernel<<<1, 64, 0, strB>>>();                                     // 6
    scan3_kernel<<<NB_SCAN, 1024, 0, strB>>>();                             // 7
    fill_kernel<<<(ETOT + 255) / 256, 256, 0, strB>>>(ei);                  // 8
    cudaEventRecord(evJoin, strB);

    cudaStreamWaitEvent(s0, evJoin, 0);
    aggregate_kernel<1><<<agg_blocks, 256, 0, s0>>>();                      // 9
    mma_gemm_kernel<128, 1><<<ggrid, 256, SM_TOTAL, s0>>>(b1, out);         // 10
    aggregate_kernel<2><<<agg_blocks, 256, 0, s0>>>();                      // 11
    mma_gemm_kernel<256, 2><<<ggrid, 256, SM_TOTAL, s0>>>(b2, out);         // 12
}